// round 4
// baseline (speedup 1.0000x reference)
#include <cuda_runtime.h>
#include <math.h>

#define PI_F 3.14159265358979323846f

// Fixed problem sizes: B=8, C=64, H=W=64, K=3, PD=576, SD=128, NQ=6, NL=2

__device__ float g_Ur[4096];   // [s][z] : column s of U, amplitude z (real)
__device__ float g_Ui[4096];   // imag
__device__ float g_style[48];  // [8][6] style angles

// ---------------------------------------------------------------------------
// Setup kernel: 256 threads, 4 threads/column, 16 register amps each.
// ---------------------------------------------------------------------------
__global__ void qcnn_setup_kernel(const float* __restrict__ style,
                                  const float* __restrict__ s2d_w,
                                  const float* __restrict__ s2d_b,
                                  const float* __restrict__ qcnn,
                                  const float* __restrict__ meas)
{
    const int tid = threadIdx.x;  // 0..255

    if (tid < 48) {
        int b = tid / 6, j = tid - 6 * b;
        float acc = s2d_b[j];
        const float* sp = style + b * 128;
        const float* wp = s2d_w + j * 128;
        #pragma unroll 8
        for (int k = 0; k < 128; k++) acc += sp[k] * wp[k];
        g_style[tid] = tanhf(acc) * PI_F;
    }

    const int c = tid >> 2;
    const int q = tid & 3;
    const unsigned FULL = 0xffffffffu;

    float ur[16], ui[16];
    #pragma unroll
    for (int zz = 0; zz < 16; zz++) {
        ur[zz] = (c == q * 16 + zz) ? 1.f : 0.f;
        ui[zz] = 0.f;
    }

    for (int l = 0; l < 2; l++) {
        #pragma unroll
        for (int i = 0; i < 6; i++) {
            const int m = 1 << (5 - i);
            float thy = qcnn[((l * 6 + i) * 2 + 0) * 3 + 0];
            float thz = qcnn[((l * 6 + i) * 2 + 1) * 3 + 0];
            float cy, sy; sincosf(0.5f * thy, &sy, &cy);
            if (m < 16) {
                #pragma unroll
                for (int zz = 0; zz < 16; zz++) {
                    if (!(zz & m)) {
                        int z1 = zz | m;
                        float r0 = ur[zz], i0 = ui[zz], r1 = ur[z1], i1 = ui[z1];
                        ur[zz] = cy * r0 - sy * r1;  ui[zz] = cy * i0 - sy * i1;
                        ur[z1] = sy * r0 + cy * r1;  ui[z1] = sy * i0 + cy * i1;
                    }
                }
            } else {
                const int lane = m >> 4;
                const int bitv = (q * 16 & m) ? 1 : 0;
                #pragma unroll
                for (int zz = 0; zz < 16; zz++) {
                    float pr = __shfl_xor_sync(FULL, ur[zz], lane);
                    float pi = __shfl_xor_sync(FULL, ui[zz], lane);
                    if (bitv == 0) {
                        ur[zz] = cy * ur[zz] - sy * pr;
                        ui[zz] = cy * ui[zz] - sy * pi;
                    } else {
                        ur[zz] = sy * pr + cy * ur[zz];
                        ui[zz] = sy * pi + cy * ui[zz];
                    }
                }
            }
            float cz, sz; sincosf(0.5f * thz, &sz, &cz);
            #pragma unroll
            for (int zz = 0; zz < 16; zz++) {
                int z = q * 16 + zz;
                float ph = (z & m) ? sz : -sz;
                float r = ur[zz], im = ui[zz];
                ur[zz] = cz * r - ph * im;
                ui[zz] = cz * im + ph * r;
            }
        }
        #pragma unroll
        for (int i = 0; i < 6; i++) {
            const int mc = 1 << (5 - i);
            const int mt = 1 << (5 - ((i + 1) % 6));
            if (mt < 16) {
                #pragma unroll
                for (int zz = 0; zz < 16; zz++) {
                    int z = q * 16 + zz;
                    if ((z & mc) && !(zz & mt)) {
                        int z2 = zz | mt;
                        float tr = ur[zz], ti = ui[zz];
                        ur[zz] = ur[z2];  ui[zz] = ui[z2];
                        ur[z2] = tr;      ui[z2] = ti;
                    }
                }
            } else {
                const int lane = mt >> 4;
                #pragma unroll
                for (int zz = 0; zz < 16; zz++) {
                    float pr = __shfl_xor_sync(FULL, ur[zz], lane);
                    float pi = __shfl_xor_sync(FULL, ui[zz], lane);
                    int z = q * 16 + zz;
                    if (z & mc) { ur[zz] = pr; ui[zz] = pi; }
                }
            }
        }
    }

    #pragma unroll
    for (int i = 0; i < 6; i++) {
        const int m = 1 << (5 - i);
        float th = meas[i * 3 + 0], ph = meas[i * 3 + 1], la = meas[i * 3 + 2];
        float ct, st; sincosf(0.5f * th, &st, &ct);
        float cl, sl; sincosf(la, &sl, &cl);
        float cp, sp; sincosf(ph, &sp, &cp);
        float cpl, spl; sincosf(ph + la, &spl, &cpl);
        float u01r = -cl * st, u01i = -sl * st;
        float u10r =  cp * st, u10i =  sp * st;
        float u11r = cpl * ct, u11i = spl * ct;
        if (m < 16) {
            #pragma unroll
            for (int zz = 0; zz < 16; zz++) {
                if (!(zz & m)) {
                    int z1 = zz | m;
                    float r0 = ur[zz], i0 = ui[zz], r1 = ur[z1], i1 = ui[z1];
                    ur[zz] = ct * r0 + u01r * r1 - u01i * i1;
                    ui[zz] = ct * i0 + u01r * i1 + u01i * r1;
                    ur[z1] = u10r * r0 - u10i * i0 + u11r * r1 - u11i * i1;
                    ui[z1] = u10r * i0 + u10i * r0 + u11r * i1 + u11i * r1;
                }
            }
        } else {
            const int lane = m >> 4;
            const int bitv = (q * 16 & m) ? 1 : 0;
            #pragma unroll
            for (int zz = 0; zz < 16; zz++) {
                float pr = __shfl_xor_sync(FULL, ur[zz], lane);
                float pi = __shfl_xor_sync(FULL, ui[zz], lane);
                float r0 = ur[zz], i0 = ui[zz];
                if (bitv == 0) {
                    ur[zz] = ct * r0 + u01r * pr - u01i * pi;
                    ui[zz] = ct * i0 + u01r * pi + u01i * pr;
                } else {
                    ur[zz] = u10r * pr - u10i * pi + u11r * r0 - u11i * i0;
                    ui[zz] = u10r * pi + u10i * pr + u11r * i0 + u11i * r0;
                }
            }
        }
    }

    #pragma unroll
    for (int zz = 0; zz < 16; zz++) {
        g_Ur[c * 64 + q * 16 + zz] = ur[zz];
        g_Ui[c * 64 + q * 16 + zz] = ui[zz];
    }
}

// ---------------------------------------------------------------------------
// Main fused kernel. 256 blocks x 640 threads, 2 CTAs/SM (regs<=48).
// Block = (batch b, 2 image rows h0, h0+1).
// Phase A: 3x3 conv 64->80 padded channels; weights staged in 2 K-chunks of
//          288 rows (92KB buffer reused). acc[2 rows][4 f32x2] = 16 regs.
// Phase B: quantum part (128 px/block) in two 8-z half-passes (16 acc regs).
// Shared memory (floats), overlaid:
//   conv: Wc[288][80]=23040, inbuf[4][16][66]=4224          (27264)
//   B:    conv_s[2][70][66]=9240, Ur/Ui 8192, a_s[128][65]=8320,
//         e_s[128][9]=1152, params 528                       (27432)
// SMEM = 27432 floats = 109728 B; 2 CTAs = 219456 <= 228KB/SM.
// ---------------------------------------------------------------------------
#define SMEM_FLOATS 27432
#define SMEM_BYTES  (SMEM_FLOATS * 4)

#define FMA2(acc, a, b) asm("fma.rn.f32x2 %0, %1, %2, %0;" : "+l"(acc) : "l"(a), "l"(b))
#define DUP2(d, f)      asm("mov.b64 %0, {%1, %1};" : "=l"(d) : "r"(__float_as_uint(f)))

__global__ __launch_bounds__(640, 2)
void qcnn_main_kernel(const float* __restrict__ x,
                      const float* __restrict__ dat_w,
                      const float* __restrict__ dat_b,
                      const float* __restrict__ out_w,
                      const float* __restrict__ out_b,
                      const float* __restrict__ res_w,
                      const float* __restrict__ res_b,
                      float* __restrict__ out)
{
    extern __shared__ float sm[];
    float* Wc    = sm;                    // [288][80]
    float* inbuf = sm + 23040;            // [4][16][66]
    // Phase-B overlay
    float* conv_s = sm;                   // [2][70][66] = 9240
    float* Urs    = sm + 9240;            // [64][64]
    float* Uis    = Urs + 4096;
    float* a_s    = Uis + 4096;           // [128][65] = 8320
    float* e_s    = a_s + 8320;           // [128][9]  = 1152
    float* pw     = e_s + 1152;           // out_w [384]
    float* pob    = pw + 384;             // out_b [64]
    float* prb    = pob + 64;             // res_b [64]
    float* pst    = prb + 64;             // style[6] @0, dat_b[6] @8

    const int tid = threadIdx.x;
    const int b   = blockIdx.x >> 5;
    const int h0  = (blockIdx.x & 31) << 1;
    const int w   = tid & 63;
    const int cg8 = (tid >> 6) * 8;       // 8-channel group base (0..72)

    unsigned long long acc[2][4];
    #pragma unroll
    for (int o = 0; o < 2; o++)
        #pragma unroll
        for (int j = 0; j < 4; j++) acc[o][j] = 0ULL;

    // --- Phase A: two 32-cin K-chunks; within each, two 16-cin quarters ---
    for (int kc = 0; kc < 2; kc++) {
        __syncthreads();  // prior chunk's readers done
        // stage weights chunk: k = kc*288 + kk, Wc[kk][c]
        const int k0 = kc * 288;
        for (int idx = tid; idx < 70 * 288; idx += 640) {
            int c  = idx / 288;
            int kk = idx - c * 288;
            int k  = k0 + kk;
            float v = (c < 64) ? res_w[c * 576 + k] : dat_w[(c - 64) * 576 + k];
            Wc[kk * 80 + c] = v;
        }
        for (int idx = tid; idx < 288 * 10; idx += 640) {
            int kk = idx / 10;
            Wc[kk * 80 + 70 + (idx - kk * 10)] = 0.f;
        }

        for (int j = 0; j < 2; j++) {
            const int cin0 = kc * 32 + j * 16;
            if (j == 1) __syncthreads();  // j0 readers done before restage
            // stage inbuf: 4 rows x 16 cin x 66
            for (int idx = tid; idx < 4224; idx += 640) {
                int r   = idx / 1056;
                int rem = idx - r * 1056;
                int ci  = rem / 66;
                int ww  = rem - ci * 66;
                int hh  = h0 + r - 1;
                int gw  = ww - 1;
                float v = 0.f;
                if (hh >= 0 && hh < 64 && gw >= 0 && gw < 64)
                    v = x[((b * 64 + cin0 + ci) * 64 + hh) * 64 + gw];
                inbuf[idx] = v;
            }
            __syncthreads();

            const float* ib    = inbuf + w;
            const float* wbase = Wc + (j * 16) * 9 * 80 + cg8;
            #pragma unroll 2
            for (int ci = 0; ci < 16; ci++) {
                #pragma unroll
                for (int dx = 0; dx < 3; dx++) {
                    unsigned long long iv2[4];
                    #pragma unroll
                    for (int r = 0; r < 4; r++) {
                        float iv = ib[(r * 16 + ci) * 66 + dx];
                        DUP2(iv2[r], iv);
                    }
                    #pragma unroll
                    for (int dy = 0; dy < 3; dy++) {
                        const ulonglong2* wp = reinterpret_cast<const ulonglong2*>(
                            wbase + (ci * 9 + dy * 3 + dx) * 80);
                        ulonglong2 wv0 = wp[0];
                        ulonglong2 wv1 = wp[1];
                        #pragma unroll
                        for (int o = 0; o < 2; o++) {
                            FMA2(acc[o][0], wv0.x, iv2[dy + o]);
                            FMA2(acc[o][1], wv0.y, iv2[dy + o]);
                            FMA2(acc[o][2], wv1.x, iv2[dy + o]);
                            FMA2(acc[o][3], wv1.y, iv2[dy + o]);
                        }
                    }
                }
            }
        }
    }
    __syncthreads();  // all Wc/inbuf readers done -> safe to overlay

    // --- Dump conv results; stage U + params ---
    #pragma unroll
    for (int o = 0; o < 2; o++) {
        #pragma unroll
        for (int jj = 0; jj < 4; jj++) {
            int c0 = cg8 + 2 * jj;
            unsigned int lo = (unsigned int)(acc[o][jj] & 0xffffffffULL);
            unsigned int hi = (unsigned int)(acc[o][jj] >> 32);
            if (c0 < 70)     conv_s[(o * 70 + c0) * 66 + w]     = __uint_as_float(lo);
            if (c0 + 1 < 70) conv_s[(o * 70 + c0 + 1) * 66 + w] = __uint_as_float(hi);
        }
    }
    for (int idx = tid; idx < 4096; idx += 640) {
        Urs[idx] = g_Ur[idx];
        Uis[idx] = g_Ui[idx];
    }
    if (tid < 384) pw[tid] = out_w[tid];
    if (tid >= 384 && tid < 448) { pob[tid - 384] = out_b[tid - 384]; prb[tid - 384] = res_b[tid - 384]; }
    if (tid >= 448 && tid < 454) { pst[tid - 448] = g_style[b * 6 + (tid - 448)]; pst[8 + tid - 448] = dat_b[tid - 448]; }
    __syncthreads();

    // --- Phase B: 512 threads = 128 pixels x 4 quarters ---
    if (tid < 512) {
        const int q  = tid & 3;
        const int p2 = tid >> 2;          // pixel 0..127
        const int o  = p2 >> 6;
        const int wq = p2 & 63;

        float cc[6], sn[6];
        #pragma unroll
        for (int i = 0; i < 6; i++) {
            float pre = conv_s[(o * 70 + 64 + i) * 66 + wq];
            float th = tanhf(pre + pst[8 + i]) * PI_F + pst[i];
            sincosf(0.5f * th, &sn[i], &cc[i]);
        }
        #pragma unroll
        for (int zz = 0; zz < 16; zz++) {
            int z = q * 16 + zz;
            float a = ((z >> 5) & 1) ? sn[0] : cc[0];
            #pragma unroll
            for (int i = 1; i < 6; i++) a *= ((z >> (5 - i)) & 1) ? sn[i] : cc[i];
            a_s[p2 * 65 + z] = a;
        }
        __syncwarp();

        // Two half-passes over z = q*16 + half*8 + t (t=0..7). 16 acc regs.
        const float* arow = a_s + p2 * 65;
        float ps[2], sb2[2], sb1[2], sb0[2];
        #pragma unroll
        for (int half = 0; half < 2; half++) {
            unsigned long long prx[4], pix[4];
            #pragma unroll
            for (int k = 0; k < 4; k++) { prx[k] = 0ULL; pix[k] = 0ULL; }
            const float* ub = Urs + q * 16 + half * 8;
            const float* vb = Uis + q * 16 + half * 8;
            #pragma unroll 8
            for (int s = 0; s < 64; s++) {
                float av = arow[s];
                unsigned long long av2;
                DUP2(av2, av);
                ulonglong2 uu = *reinterpret_cast<const ulonglong2*>(ub + s * 64);
                ulonglong2 u2 = *reinterpret_cast<const ulonglong2*>(ub + s * 64 + 4);
                ulonglong2 vv = *reinterpret_cast<const ulonglong2*>(vb + s * 64);
                ulonglong2 v2 = *reinterpret_cast<const ulonglong2*>(vb + s * 64 + 4);
                FMA2(prx[0], uu.x, av2);
                FMA2(prx[1], uu.y, av2);
                FMA2(prx[2], u2.x, av2);
                FMA2(prx[3], u2.y, av2);
                FMA2(pix[0], vv.x, av2);
                FMA2(pix[1], vv.y, av2);
                FMA2(pix[2], v2.x, av2);
                FMA2(pix[3], v2.y, av2);
            }
            float h_ps = 0.f, h_b2 = 0.f, h_b1 = 0.f, h_b0 = 0.f;
            #pragma unroll
            for (int k = 0; k < 4; k++) {   // t = 2k, 2k+1
                unsigned int rlo, rhi, ilo, ihi;
                asm("mov.b64 {%0,%1}, %2;" : "=r"(rlo), "=r"(rhi) : "l"(prx[k]));
                asm("mov.b64 {%0,%1}, %2;" : "=r"(ilo), "=r"(ihi) : "l"(pix[k]));
                float r0 = __uint_as_float(rlo), r1 = __uint_as_float(rhi);
                float i0 = __uint_as_float(ilo), i1 = __uint_as_float(ihi);
                float p0 = r0 * r0 + i0 * i0;
                float p1 = r1 * r1 + i1 * i1;
                float pp = p0 + p1;
                h_ps += pp;
                h_b2 += (k & 2) ? -pp : pp;   // bit2 of t
                h_b1 += (k & 1) ? -pp : pp;   // bit1 of t
                h_b0 += p0 - p1;              // bit0 of t
            }
            ps[half] = h_ps; sb2[half] = h_b2; sb1[half] = h_b1; sb0[half] = h_b0;
        }
        float e[6];
        float pt = ps[0] + ps[1];
        e[0] = (q & 2) ? -pt : pt;            // bit5 = q>>1
        e[1] = (q & 1) ? -pt : pt;            // bit4 = q&1
        e[2] = ps[0] - ps[1];                 // bit3 = half
        e[3] = sb2[0] + sb2[1];               // bit2
        e[4] = sb1[0] + sb1[1];               // bit1
        e[5] = sb0[0] + sb0[1];               // bit0
        #pragma unroll
        for (int i = 0; i < 6; i++) {
            e[i] += __shfl_xor_sync(0xffffffffu, e[i], 1);
            e[i] += __shfl_xor_sync(0xffffffffu, e[i], 2);
        }
        if (q == 0) {
            #pragma unroll
            for (int i = 0; i < 6; i++) e_s[p2 * 9 + i] = e[i];
        }
    }
    __syncthreads();

    // --- Epilogue: 512 threads = (pixel w, 8-ch group), 2 rows each ---
    if (tid < 512) {
        const int wE  = tid & 63;
        const int cgE = tid >> 6;     // 0..7
        #pragma unroll
        for (int o = 0; o < 2; o++) {
            float ev[6];
            #pragma unroll
            for (int i = 0; i < 6; i++) ev[i] = e_s[(o * 64 + wE) * 9 + i];
            #pragma unroll
            for (int j = 0; j < 8; j++) {
                int c = cgE * 8 + j;
                float v = conv_s[(o * 70 + c) * 66 + wE] + pob[c] + prb[c];
                #pragma unroll
                for (int i = 0; i < 6; i++) v += pw[c * 6 + i] * ev[i];
                out[((b * 64 + c) * 64 + (h0 + o)) * 64 + wE] = v;
            }
        }
    }
}

// ---------------------------------------------------------------------------
extern "C" void kernel_launch(void* const* d_in, const int* in_sizes, int n_in,
                              void* d_out, int out_size)
{
    (void)in_sizes; (void)n_in; (void)out_size;
    const float* x      = (const float*)d_in[0];
    const float* style  = (const float*)d_in[1];
    const float* dat_w  = (const float*)d_in[2];
    const float* dat_b  = (const float*)d_in[3];
    const float* s2d_w  = (const float*)d_in[4];
    const float* s2d_b  = (const float*)d_in[5];
    const float* qcnn   = (const float*)d_in[6];
    const float* meas   = (const float*)d_in[7];
    const float* out_w  = (const float*)d_in[8];
    const float* out_b  = (const float*)d_in[9];
    const float* res_w  = (const float*)d_in[10];
    const float* res_b  = (const float*)d_in[11];
    float* out = (float*)d_out;

    cudaFuncSetAttribute(qcnn_main_kernel,
                         cudaFuncAttributeMaxDynamicSharedMemorySize, SMEM_BYTES);

    qcnn_setup_kernel<<<1, 256>>>(style, s2d_w, s2d_b, qcnn, meas);
    qcnn_main_kernel<<<256, 640, SMEM_BYTES>>>(x, dat_w, dat_b, out_w, out_b,
                                               res_w, res_b, out);
}